// round 9
// baseline (speedup 1.0000x reference)
#include <cuda_runtime.h>
#include <math.h>

// Shapes fixed by the problem
#define BATCH 8
#define CCH   1024
#define LL    4096
#define NPB   (CCH*LL)            // 4,194,304 elements per batch
#define NBL   (BATCH*LL)          // 32,768 (b,l) pairs

// Scratch (no allocations allowed)
__device__ double g_bsum[BATCH];
__device__ double g_bsumsq[BATCH];
__device__ double g_loss;
__device__ float  g_margin[BATCH];
__device__ __align__(16) float g_zs[NBL];   // later: 1/zs
__device__ __align__(16) float g_zt[NBL];   // later: log zt

// ---------------------------------------------------------------------------
// K0: zero all accumulators (graph replay safe). 128 blocks x 256.
// ---------------------------------------------------------------------------
__global__ void __launch_bounds__(256) k_zero() {
  int i = blockIdx.x * 256 + threadIdx.x;   // 0..32767
  g_zs[i] = 0.f;
  g_zt[i] = 0.f;
  if (i < BATCH) { g_bsum[i] = 0.0; g_bsumsq[i] = 0.0; }
  if (i == 0) g_loss = 0.0;
}

// ---------------------------------------------------------------------------
// K_A: fused pass over xs and xt.
//   - zs[b,l] += sum_c exp(xs[b,c,l])     (no max subtraction; safe in fp32)
//   - per-batch sum / sumsq of xt         (for margin)
// Grid: 1024 blocks = 8 b x 4 lt(1024) x 32 cc(32 c's each). Block 256 thr,
// thread owns 4 consecutive l (float4). Fully coalesced.
// xs is read with __ldcs (streaming) so L2 retains xt for k_C.
// ---------------------------------------------------------------------------
__global__ void __launch_bounds__(256) k_A(const float* __restrict__ xs,
                                           const float* __restrict__ xt) {
  int bid = blockIdx.x;
  int cc = bid & 31;
  int lt = (bid >> 5) & 3;
  int b  = bid >> 7;
  int t  = threadIdx.x;
  int l  = lt * 1024 + t * 4;

  size_t base = (size_t)b * NPB + (size_t)(cc * 32) * LL + l;
  const float4* ps = reinterpret_cast<const float4*>(xs + base);
  const float4* pt = reinterpret_cast<const float4*>(xt + base);

  float z0 = 0.f, z1 = 0.f, z2 = 0.f, z3 = 0.f;
  float s = 0.f, s2 = 0.f;
#pragma unroll 4
  for (int c = 0; c < 32; c++) {
    float4 a = __ldcs(ps + (size_t)c * (LL/4));   // streaming: don't pollute L2
    float4 w = pt[(size_t)c * (LL/4)];            // normal: retain xt in L2
    z0 += __expf(a.x); z1 += __expf(a.y);
    z2 += __expf(a.z); z3 += __expf(a.w);
    s  += (w.x + w.y) + (w.z + w.w);
    s2 += (w.x*w.x + w.y*w.y) + (w.z*w.z + w.w*w.w);
  }

  float* zp = &g_zs[b * LL + l];
  atomicAdd(zp + 0, z0); atomicAdd(zp + 1, z1);
  atomicAdd(zp + 2, z2); atomicAdd(zp + 3, z3);

  // block reduce stats -> double atomics
#pragma unroll
  for (int o = 16; o; o >>= 1) {
    s  += __shfl_xor_sync(0xffffffffu, s,  o);
    s2 += __shfl_xor_sync(0xffffffffu, s2, o);
  }
  __shared__ float ws[8], ws2[8];
  int warp = t >> 5, lane = t & 31;
  if (lane == 0) { ws[warp] = s; ws2[warp] = s2; }
  __syncthreads();
  if (t == 0) {
    float ts = 0.f, ts2 = 0.f;
#pragma unroll
    for (int w = 0; w < 8; w++) { ts += ws[w]; ts2 += ws2[w]; }
    atomicAdd(&g_bsum[b],   (double)ts);
    atomicAdd(&g_bsumsq[b], (double)ts2);
  }
}

// ---------------------------------------------------------------------------
// K_margin: finalize margin per batch (double precision, 8 scalars)
// ---------------------------------------------------------------------------
__global__ void k_margin() {
  int b = threadIdx.x;
  if (b >= BATCH) return;
  const double N = (double)NPB;
  double s = g_bsum[b], s2 = g_bsumsq[b];
  double mean = s / N;
  double var  = (s2 - s*s/N) / (N - 1.0);   // unbiased (ddof=1)
  double sd   = sqrt(fabs(var));
  double z    = -mean / sd;
  double cdf  = 0.5 * (1.0 + erf(z * 0.70710678118654752440));
  double safe = fmax(cdf, 1e-30);
  double ma   = -sd * exp(-(mean/sd)*(mean/sd)*0.5)
                / 2.50662827463100050241 / safe + mean;
  double m    = (cdf > 0.001) ? ma : (-3.0 * sd);
  g_margin[b] = (float)m;
}

// ---------------------------------------------------------------------------
// K_C: zt[b,l] = sum_c exp(max(xt[b,c,l], margin[b])).
// Same block mapping as K_A but the c-loop runs in REVERSE so each block
// starts exactly where its K_A counterpart's xt stream ended (L2-hot).
// ---------------------------------------------------------------------------
__global__ void __launch_bounds__(256) k_C(const float* __restrict__ xt) {
  int bid = blockIdx.x;
  int cc = bid & 31;
  int lt = (bid >> 5) & 3;
  int b  = bid >> 7;
  int t  = threadIdx.x;
  int l  = lt * 1024 + t * 4;
  float m = g_margin[b];

  size_t base = (size_t)b * NPB + (size_t)(cc * 32) * LL + l;
  const float4* pt = reinterpret_cast<const float4*>(xt + base);

  float z0 = 0.f, z1 = 0.f, z2 = 0.f, z3 = 0.f;
#pragma unroll 4
  for (int c = 31; c >= 0; c--) {   // reversed: walk back through L2-resident tail
    float4 w = pt[(size_t)c * (LL/4)];
    z0 += __expf(fmaxf(w.x, m)); z1 += __expf(fmaxf(w.y, m));
    z2 += __expf(fmaxf(w.z, m)); z3 += __expf(fmaxf(w.w, m));
  }
  float* zp = &g_zt[b * LL + l];
  atomicAdd(zp + 0, z0); atomicAdd(zp + 1, z1);
  atomicAdd(zp + 2, z2); atomicAdd(zp + 3, z3);
}

// ---------------------------------------------------------------------------
// K_tab: g_zs <- 1/zs, g_zt <- log(zt). 32K elements, in place.
// ---------------------------------------------------------------------------
__global__ void __launch_bounds__(256) k_tab() {
  int i = blockIdx.x * 256 + threadIdx.x;
  g_zs[i] = 1.0f / g_zs[i];
  g_zt[i] = logf(g_zt[i]);
}

// ---------------------------------------------------------------------------
// K_D: elementwise entropy + writeout + loss.
//   e = exp(xs) * invzs * (max(xt, margin) - lzt)
// Same mapping, forward c (k_C leaves xt ~fully L2-resident). xs read with
// __ldcs and output written with __stcs so neither evicts the xt working set.
// Output stores are scalar (d_out+1 is only 4B-aligned).
// ---------------------------------------------------------------------------
__global__ void __launch_bounds__(256) k_D(const float* __restrict__ xs,
                                           const float* __restrict__ xt,
                                           float* __restrict__ eout) {
  int bid = blockIdx.x;
  int cc = bid & 31;
  int lt = (bid >> 5) & 3;
  int b  = bid >> 7;
  int t  = threadIdx.x;
  int l  = lt * 1024 + t * 4;

  float4 iz = *reinterpret_cast<const float4*>(&g_zs[b * LL + l]);
  float4 lz = *reinterpret_cast<const float4*>(&g_zt[b * LL + l]);
  float m = g_margin[b];

  size_t base = (size_t)b * NPB + (size_t)(cc * 32) * LL + l;
  const float4* ps = reinterpret_cast<const float4*>(xs + base);
  const float4* pt = reinterpret_cast<const float4*>(xt + base);
  float* po = eout + base;

  float acc = 0.f;
#pragma unroll 4
  for (int c = 0; c < 32; c++) {
    float4 a = __ldcs(ps + (size_t)c * (LL/4));  // streaming
    float4 w = pt[(size_t)c * (LL/4)];           // L2-hot from k_C
    float e0 = __expf(a.x) * iz.x * (fmaxf(w.x, m) - lz.x);
    float e1 = __expf(a.y) * iz.y * (fmaxf(w.y, m) - lz.y);
    float e2 = __expf(a.z) * iz.z * (fmaxf(w.z, m) - lz.z);
    float e3 = __expf(a.w) * iz.w * (fmaxf(w.w, m) - lz.w);
    float* d = po + (size_t)c * LL;
    __stcs(d + 0, e0); __stcs(d + 1, e1);
    __stcs(d + 2, e2); __stcs(d + 3, e3);
    acc += (e0 + e1) + (e2 + e3);
  }

#pragma unroll
  for (int o = 16; o; o >>= 1) acc += __shfl_xor_sync(0xffffffffu, acc, o);
  __shared__ float wacc[8];
  int warp = t >> 5, lane = t & 31;
  if (lane == 0) wacc[warp] = acc;
  __syncthreads();
  if (t == 0) {
    float ts = 0.f;
#pragma unroll
    for (int w = 0; w < 8; w++) ts += wacc[w];
    atomicAdd(&g_loss, (double)ts);
  }
}

// ---------------------------------------------------------------------------
// K_loss: loss = -total / (B*L)
// ---------------------------------------------------------------------------
__global__ void k_loss(float* __restrict__ out0) {
  if (threadIdx.x == 0) out0[0] = (float)(-g_loss / (double)(BATCH * LL));
}

// ---------------------------------------------------------------------------
extern "C" void kernel_launch(void* const* d_in, const int* in_sizes, int n_in,
                              void* d_out, int out_size) {
  // metadata order: x_s, x_t, x_ts, x_st, i
  const float* xs = (const float*)d_in[2];  // x_ts -> source
  const float* xt = (const float*)d_in[3];  // x_st -> target (margin source)
  float* out = (float*)d_out;               // [0] = loss, [1..] = entropy [B,C,L]

  k_zero  <<<NBL/256, 256>>>();
  k_A     <<<1024, 256>>>(xs, xt);
  k_margin<<<1, 32>>>();
  k_C     <<<1024, 256>>>(xt);
  k_tab   <<<NBL/256, 256>>>();
  k_D     <<<1024, 256>>>(xs, xt, out + 1);
  k_loss  <<<1, 32>>>(out);
}

// round 10
// speedup vs baseline: 1.0835x; 1.0835x over previous
#include <cuda_runtime.h>
#include <cuda_fp16.h>
#include <math.h>

// Shapes fixed by the problem
#define BATCH 8
#define CCH   1024
#define LL    4096
#define NPB   (CCH*LL)            // 4,194,304 elements per batch
#define NBL   (BATCH*LL)          // 32,768 (b,l) pairs

// Scratch (no allocations allowed)
__device__ double g_bsum[BATCH];
__device__ double g_bsumsq[BATCH];
__device__ double g_loss;
__device__ float  g_margin[BATCH];
__device__ __align__(16) float g_zs[NBL];            // raw sum exp(xs)
__device__ __align__(16) float g_zt[NBL];            // raw sum exp(max(xt,m))
__device__ __align__(16) __half g_xt16[BATCH*NPB];   // fp16 shadow of xt (64 MiB)

// ---------------------------------------------------------------------------
// K0: zero all accumulators (graph replay safe). 128 blocks x 256.
// ---------------------------------------------------------------------------
__global__ void __launch_bounds__(256) k_zero() {
  int i = blockIdx.x * 256 + threadIdx.x;   // 0..32767
  g_zs[i] = 0.f;
  g_zt[i] = 0.f;
  if (i < BATCH) { g_bsum[i] = 0.0; g_bsumsq[i] = 0.0; }
  if (i == 0) g_loss = 0.0;
}

// ---------------------------------------------------------------------------
// K_A: single fp32 pass over xs and xt.
//   - zs[b,l] += sum_c exp(xs[b,c,l])   (no max subtraction; safe in fp32)
//   - per-batch sum / sumsq of xt       (for margin)
//   - writes xt16 shadow copy (the only fp32 read of xt in the pipeline)
// Grid: 1024 blocks = 8 b x 4 lt(1024 l) x 32 cc(32 c). Thread owns 4 l.
// ---------------------------------------------------------------------------
__global__ void __launch_bounds__(256) k_A(const float* __restrict__ xs,
                                           const float* __restrict__ xt) {
  int bid = blockIdx.x;
  int cc = bid & 31;
  int lt = (bid >> 5) & 3;
  int b  = bid >> 7;
  int t  = threadIdx.x;
  int l  = lt * 1024 + t * 4;

  size_t base = (size_t)b * NPB + (size_t)(cc * 32) * LL + l;
  const float4* ps = reinterpret_cast<const float4*>(xs + base);
  const float4* pt = reinterpret_cast<const float4*>(xt + base);
  uint2* ph = reinterpret_cast<uint2*>(g_xt16 + base);   // 4 halfs = 8B

  float z0 = 0.f, z1 = 0.f, z2 = 0.f, z3 = 0.f;
  float s = 0.f, s2 = 0.f;
#pragma unroll 4
  for (int c = 0; c < 32; c++) {
    float4 a = __ldcs(ps + (size_t)c * (LL/4));   // fp32 xs: last use
    float4 w = __ldcs(pt + (size_t)c * (LL/4));   // fp32 xt: last use
    z0 += __expf(a.x); z1 += __expf(a.y);
    z2 += __expf(a.z); z3 += __expf(a.w);
    s  += (w.x + w.y) + (w.z + w.w);
    s2 += (w.x*w.x + w.y*w.y) + (w.z*w.z + w.w*w.w);
    __half2 h01 = __floats2half2_rn(w.x, w.y);
    __half2 h23 = __floats2half2_rn(w.z, w.w);
    uint2 hv;
    hv.x = *reinterpret_cast<unsigned*>(&h01);
    hv.y = *reinterpret_cast<unsigned*>(&h23);
    ph[(size_t)c * (LL/4)] = hv;                  // cached: re-read by k_C/k_D
  }

  float* zp = &g_zs[b * LL + l];
  atomicAdd(zp + 0, z0); atomicAdd(zp + 1, z1);
  atomicAdd(zp + 2, z2); atomicAdd(zp + 3, z3);

  // block reduce stats -> double atomics
#pragma unroll
  for (int o = 16; o; o >>= 1) {
    s  += __shfl_xor_sync(0xffffffffu, s,  o);
    s2 += __shfl_xor_sync(0xffffffffu, s2, o);
  }
  __shared__ float ws[8], ws2[8];
  int warp = t >> 5, lane = t & 31;
  if (lane == 0) { ws[warp] = s; ws2[warp] = s2; }
  __syncthreads();
  if (t == 0) {
    float ts = 0.f, ts2 = 0.f;
#pragma unroll
    for (int w = 0; w < 8; w++) { ts += ws[w]; ts2 += ws2[w]; }
    atomicAdd(&g_bsum[b],   (double)ts);
    atomicAdd(&g_bsumsq[b], (double)ts2);
  }
}

// ---------------------------------------------------------------------------
// K_margin: finalize margin per batch (double precision, 8 scalars)
// ---------------------------------------------------------------------------
__global__ void k_margin() {
  int b = threadIdx.x;
  if (b >= BATCH) return;
  const double N = (double)NPB;
  double s = g_bsum[b], s2 = g_bsumsq[b];
  double mean = s / N;
  double var  = (s2 - s*s/N) / (N - 1.0);   // unbiased (ddof=1)
  double sd   = sqrt(fabs(var));
  double z    = -mean / sd;
  double cdf  = 0.5 * (1.0 + erf(z * 0.70710678118654752440));
  double safe = fmax(cdf, 1e-30);
  double ma   = -sd * exp(-(mean/sd)*(mean/sd)*0.5)
                / 2.50662827463100050241 / safe + mean;
  double m    = (cdf > 0.001) ? ma : (-3.0 * sd);
  g_margin[b] = (float)m;
}

// ---------------------------------------------------------------------------
// K_C: zt[b,l] = sum_c exp(max(xt16[b,c,l], margin[b])). Reads only fp16.
// Grid: 512 blocks = 8 b x 2 lt(2048 l) x 32 cc(32 c). Thread owns 8 l (uint4).
// ---------------------------------------------------------------------------
__global__ void __launch_bounds__(256) k_C() {
  int bid = blockIdx.x;
  int cc = bid & 31;
  int lt = (bid >> 5) & 1;
  int b  = bid >> 6;
  int t  = threadIdx.x;
  int l  = lt * 2048 + t * 8;
  float m = g_margin[b];

  size_t base = (size_t)b * NPB + (size_t)(cc * 32) * LL + l;
  const uint4* ph = reinterpret_cast<const uint4*>(g_xt16 + base);  // 8 halfs

  float z[8];
#pragma unroll
  for (int j = 0; j < 8; j++) z[j] = 0.f;

#pragma unroll 4
  for (int c = 0; c < 32; c++) {
    uint4 hv = ph[(size_t)c * (LL/8)];
    float2 f0 = __half22float2(*reinterpret_cast<__half2*>(&hv.x));
    float2 f1 = __half22float2(*reinterpret_cast<__half2*>(&hv.y));
    float2 f2 = __half22float2(*reinterpret_cast<__half2*>(&hv.z));
    float2 f3 = __half22float2(*reinterpret_cast<__half2*>(&hv.w));
    z[0] += __expf(fmaxf(f0.x, m)); z[1] += __expf(fmaxf(f0.y, m));
    z[2] += __expf(fmaxf(f1.x, m)); z[3] += __expf(fmaxf(f1.y, m));
    z[4] += __expf(fmaxf(f2.x, m)); z[5] += __expf(fmaxf(f2.y, m));
    z[6] += __expf(fmaxf(f3.x, m)); z[7] += __expf(fmaxf(f3.y, m));
  }
  float* zp = &g_zt[b * LL + l];
#pragma unroll
  for (int j = 0; j < 8; j++) atomicAdd(zp + j, z[j]);
}

// ---------------------------------------------------------------------------
// K_D: elementwise entropy + writeout + loss. k_tab folded in (per-thread
// rcp/log of the 4 owned (b,l) table entries, amortized over 32 c's).
//   e = exp(xs) * (1/zs) * (max(xt16, margin) - log zt)
// xs streamed (last fp32 read), xt16 last use, output streamed.
// ---------------------------------------------------------------------------
__global__ void __launch_bounds__(256) k_D(const float* __restrict__ xs,
                                           float* __restrict__ eout) {
  int bid = blockIdx.x;
  int cc = bid & 31;
  int lt = (bid >> 5) & 3;
  int b  = bid >> 7;
  int t  = threadIdx.x;
  int l  = lt * 1024 + t * 4;

  float4 zs4 = *reinterpret_cast<const float4*>(&g_zs[b * LL + l]);
  float4 zt4 = *reinterpret_cast<const float4*>(&g_zt[b * LL + l]);
  float4 iz, lz;
  iz.x = __fdividef(1.f, zs4.x); iz.y = __fdividef(1.f, zs4.y);
  iz.z = __fdividef(1.f, zs4.z); iz.w = __fdividef(1.f, zs4.w);
  lz.x = __logf(zt4.x); lz.y = __logf(zt4.y);
  lz.z = __logf(zt4.z); lz.w = __logf(zt4.w);
  float m = g_margin[b];

  size_t base = (size_t)b * NPB + (size_t)(cc * 32) * LL + l;
  const float4* ps = reinterpret_cast<const float4*>(xs + base);
  const uint2*  ph = reinterpret_cast<const uint2*>(g_xt16 + base);
  float* po = eout + base;

  float acc = 0.f;
#pragma unroll 4
  for (int c = 0; c < 32; c++) {
    float4 a = __ldcs(ps + (size_t)c * (LL/4));      // streaming fp32 xs
    uint2 hv = __ldcs(ph + (size_t)c * (LL/4));      // last use of xt16
    float2 w01 = __half22float2(*reinterpret_cast<__half2*>(&hv.x));
    float2 w23 = __half22float2(*reinterpret_cast<__half2*>(&hv.y));
    float e0 = __expf(a.x) * iz.x * (fmaxf(w01.x, m) - lz.x);
    float e1 = __expf(a.y) * iz.y * (fmaxf(w01.y, m) - lz.y);
    float e2 = __expf(a.z) * iz.z * (fmaxf(w23.x, m) - lz.z);
    float e3 = __expf(a.w) * iz.w * (fmaxf(w23.y, m) - lz.w);
    float* d = po + (size_t)c * LL;
    __stcs(d + 0, e0); __stcs(d + 1, e1);
    __stcs(d + 2, e2); __stcs(d + 3, e3);
    acc += (e0 + e1) + (e2 + e3);
  }

#pragma unroll
  for (int o = 16; o; o >>= 1) acc += __shfl_xor_sync(0xffffffffu, acc, o);
  __shared__ float wacc[8];
  int warp = t >> 5, lane = t & 31;
  if (lane == 0) wacc[warp] = acc;
  __syncthreads();
  if (t == 0) {
    float ts = 0.f;
#pragma unroll
    for (int w = 0; w < 8; w++) ts += wacc[w];
    atomicAdd(&g_loss, (double)ts);
  }
}

// ---------------------------------------------------------------------------
// K_loss: loss = -total / (B*L)
// ---------------------------------------------------------------------------
__global__ void k_loss(float* __restrict__ out0) {
  if (threadIdx.x == 0) out0[0] = (float)(-g_loss / (double)(BATCH * LL));
}

// ---------------------------------------------------------------------------
extern "C" void kernel_launch(void* const* d_in, const int* in_sizes, int n_in,
                              void* d_out, int out_size) {
  // metadata order: x_s, x_t, x_ts, x_st, i
  const float* xs = (const float*)d_in[2];  // x_ts -> source
  const float* xt = (const float*)d_in[3];  // x_st -> target (margin source)
  float* out = (float*)d_out;               // [0] = loss, [1..] = entropy [B,C,L]

  k_zero  <<<NBL/256, 256>>>();
  k_A     <<<1024, 256>>>(xs, xt);
  k_margin<<<1, 32>>>();
  k_C     <<<512, 256>>>();
  k_D     <<<1024, 256>>>(xs, out + 1);
  k_loss  <<<1, 32>>>(out);
}